// round 8
// baseline (speedup 1.0000x reference)
#include <cuda_runtime.h>
#include <math.h>

#define HEADS 8
#define MAXN 4096
#define MAXW 2048
#define MAXEP 65536
#define LN_EPS 1e-5f

// ---------------- scratch (static device memory; no runtime alloc) -------------
__device__ float g_H[(size_t)MAXN * MAXW];     // h = x @ W
__device__ float g_X[(size_t)MAXN * MAXW];     // layer activations
__device__ float g_P[(size_t)MAXN * 256];      // projection out
__device__ float g_AL[MAXN * HEADS];
__device__ float g_AR[MAXN * HEADS];
__device__ float g_Q[MAXN];
__device__ float g_RED[2];
__device__ int   g_DEG[MAXN];
__device__ int   g_ROW[MAXN + 1];
__device__ int   g_CUR[MAXN];
__device__ int   g_CSRC[MAXEP];

// ---------------- CSR build ----------------------------------------------------
__global__ void zero_int(int* p, int n) {
    int i = blockIdx.x * blockDim.x + threadIdx.x;
    if (i < n) p[i] = 0;
}
__global__ void deg_count(const int* __restrict__ dst, int* deg, int E) {
    int i = blockIdx.x * blockDim.x + threadIdx.x;
    if (i < E) atomicAdd(&deg[dst[i]], 1);
}
// single-block exclusive scan over N<=4096 (1024 threads x 4 elems)
__global__ void scan_kernel(const int* __restrict__ deg, int* rowptr, int* cursor, int N) {
    __shared__ int sh[1024];
    int tid = threadIdx.x;
    int start = tid * 4;
    int local[4];
    int sum = 0;
#pragma unroll
    for (int i = 0; i < 4; i++) {
        int idx = start + i;
        local[i] = (idx < N) ? deg[idx] : 0;
        sum += local[i];
    }
    sh[tid] = sum;
    __syncthreads();
    for (int off = 1; off < 1024; off <<= 1) {
        int v = (tid >= off) ? sh[tid - off] : 0;
        __syncthreads();
        sh[tid] += v;
        __syncthreads();
    }
    int run = sh[tid] - sum;  // exclusive
#pragma unroll
    for (int i = 0; i < 4; i++) {
        int idx = start + i;
        if (idx < N) { rowptr[idx] = run; cursor[idx] = run; run += local[i]; }
    }
    if (tid == 1023) rowptr[N] = sh[1023];
}
__global__ void scatter_kernel(const int* __restrict__ src, const int* __restrict__ dst,
                               int* cursor, int* csrc, int E) {
    int i = blockIdx.x * blockDim.x + threadIdx.x;
    if (i < E) {
        int pos = atomicAdd(&cursor[dst[i]], 1);
        csrc[pos] = src[i];
    }
}

// ---------------- tf32 tensor-core GEMM v2: 64x128x32, reg double-buffer ------
// 256 threads = 8 warps (2m x 4n), warp tile 32x32 = 2(m16) x 4(n8) frags.
#define TBM 64
#define TBN 128
#define TBK 32
#define ASTR 36   // bank(a-frag LDS) = 4*gid + tig (+4) -> conflict-free
#define BSTR 136  // bank(b-frag LDS) = 8*tig + gid + nb -> conflict-free

__device__ __forceinline__ unsigned f2tf32(float x) {
    unsigned r;
    asm("cvt.rna.tf32.f32 %0, %1;" : "=r"(r) : "f"(x));
    return r;
}

__global__ void gemm_tf32_kernel(const float* __restrict__ A, const float* __restrict__ B,
                                 const float* __restrict__ bias, float* __restrict__ C,
                                 int M, int N, int K) {
    __shared__ unsigned As[TBM][ASTR];
    __shared__ unsigned Bs[TBK][BSTR];
    const int tid = threadIdx.x;
    const int warp = tid >> 5, lane = tid & 31;
    const int wm = warp >> 2, wn = warp & 3;
    const int gid = lane >> 2, tig = lane & 3;
    const int rowBase = blockIdx.y * TBM;
    const int colBase = blockIdx.x * TBN;

    // A tile: 64x32 = 512 float4, 2/thread. B tile: 32x128 = 1024 float4, 4/thread.
    const int ar0 = tid >> 3,        ac0 = (tid & 7) << 2;          // p=0
    const int ar1 = (tid + 256) >> 3, ac1 = ((tid + 256) & 7) << 2; // p=1
    float4 aReg[2], bReg[4];

    float c[2][4][4];
#pragma unroll
    for (int mi = 0; mi < 2; mi++)
#pragma unroll
        for (int ni = 0; ni < 4; ni++)
#pragma unroll
            for (int f = 0; f < 4; f++) c[mi][ni][f] = 0.f;

    // ---- prologue: load k-tile 0 ----
    {
        int gr0 = rowBase + ar0, gr1 = rowBase + ar1;
        aReg[0] = (gr0 < M) ? *(const float4*)&A[(size_t)gr0 * K + ac0]
                            : make_float4(0.f, 0.f, 0.f, 0.f);
        aReg[1] = (gr1 < M) ? *(const float4*)&A[(size_t)gr1 * K + ac1]
                            : make_float4(0.f, 0.f, 0.f, 0.f);
#pragma unroll
        for (int p = 0; p < 4; p++) {
            int i = tid + p * 256;
            int r = i >> 5, cc = (i & 31) << 2;
            bReg[p] = *(const float4*)&B[(size_t)r * N + colBase + cc];
        }
    }
    // store tile 0 to smem
    {
        uint4 u;
        u.x = f2tf32(aReg[0].x); u.y = f2tf32(aReg[0].y); u.z = f2tf32(aReg[0].z); u.w = f2tf32(aReg[0].w);
        *(uint4*)&As[ar0][ac0] = u;
        u.x = f2tf32(aReg[1].x); u.y = f2tf32(aReg[1].y); u.z = f2tf32(aReg[1].z); u.w = f2tf32(aReg[1].w);
        *(uint4*)&As[ar1][ac1] = u;
#pragma unroll
        for (int p = 0; p < 4; p++) {
            int i = tid + p * 256;
            int r = i >> 5, cc = (i & 31) << 2;
            uint4 v;
            v.x = f2tf32(bReg[p].x); v.y = f2tf32(bReg[p].y); v.z = f2tf32(bReg[p].z); v.w = f2tf32(bReg[p].w);
            *(uint4*)&Bs[r][cc] = v;
        }
    }
    __syncthreads();

    for (int k0 = 0; k0 < K; k0 += TBK) {
        const bool has_next = (k0 + TBK) < K;
        // ---- issue next tile's global loads (overlap with MMA below) ----
        if (has_next) {
            int kn = k0 + TBK;
            int gr0 = rowBase + ar0, gr1 = rowBase + ar1;
            aReg[0] = (gr0 < M) ? *(const float4*)&A[(size_t)gr0 * K + kn + ac0]
                                : make_float4(0.f, 0.f, 0.f, 0.f);
            aReg[1] = (gr1 < M) ? *(const float4*)&A[(size_t)gr1 * K + kn + ac1]
                                : make_float4(0.f, 0.f, 0.f, 0.f);
#pragma unroll
            for (int p = 0; p < 4; p++) {
                int i = tid + p * 256;
                int r = i >> 5, cc = (i & 31) << 2;
                bReg[p] = *(const float4*)&B[(size_t)(kn + r) * N + colBase + cc];
            }
        }

        // ---- compute current tile from smem ----
#pragma unroll
        for (int ks = 0; ks < TBK; ks += 8) {
            unsigned a[2][4], b[4][2];
#pragma unroll
            for (int mi = 0; mi < 2; mi++) {
                int mb = wm * 32 + mi * 16;
                a[mi][0] = As[mb + gid][ks + tig];
                a[mi][1] = As[mb + gid + 8][ks + tig];
                a[mi][2] = As[mb + gid][ks + tig + 4];
                a[mi][3] = As[mb + gid + 8][ks + tig + 4];
            }
#pragma unroll
            for (int ni = 0; ni < 4; ni++) {
                int nb = wn * 32 + ni * 8;
                b[ni][0] = Bs[ks + tig][nb + gid];
                b[ni][1] = Bs[ks + tig + 4][nb + gid];
            }
#pragma unroll
            for (int mi = 0; mi < 2; mi++)
#pragma unroll
                for (int ni = 0; ni < 4; ni++) {
                    asm volatile(
                        "mma.sync.aligned.m16n8k8.row.col.f32.tf32.tf32.f32 "
                        "{%0,%1,%2,%3}, {%4,%5,%6,%7}, {%8,%9}, {%0,%1,%2,%3};"
                        : "+f"(c[mi][ni][0]), "+f"(c[mi][ni][1]),
                          "+f"(c[mi][ni][2]), "+f"(c[mi][ni][3])
                        : "r"(a[mi][0]), "r"(a[mi][1]), "r"(a[mi][2]), "r"(a[mi][3]),
                          "r"(b[ni][0]), "r"(b[ni][1]));
                }
        }
        __syncthreads();

        // ---- commit next tile to smem ----
        if (has_next) {
            uint4 u;
            u.x = f2tf32(aReg[0].x); u.y = f2tf32(aReg[0].y); u.z = f2tf32(aReg[0].z); u.w = f2tf32(aReg[0].w);
            *(uint4*)&As[ar0][ac0] = u;
            u.x = f2tf32(aReg[1].x); u.y = f2tf32(aReg[1].y); u.z = f2tf32(aReg[1].z); u.w = f2tf32(aReg[1].w);
            *(uint4*)&As[ar1][ac1] = u;
#pragma unroll
            for (int p = 0; p < 4; p++) {
                int i = tid + p * 256;
                int r = i >> 5, cc = (i & 31) << 2;
                uint4 v;
                v.x = f2tf32(bReg[p].x); v.y = f2tf32(bReg[p].y); v.z = f2tf32(bReg[p].z); v.w = f2tf32(bReg[p].w);
                *(uint4*)&Bs[r][cc] = v;
            }
            __syncthreads();
        }
    }

    // ---- store ----
#pragma unroll
    for (int mi = 0; mi < 2; mi++) {
        int r0 = rowBase + wm * 32 + mi * 16 + gid;
#pragma unroll
        for (int ni = 0; ni < 4; ni++) {
            int col = colBase + wn * 32 + ni * 8 + tig * 2;
            float b0 = bias ? bias[col] : 0.f;
            float b1 = bias ? bias[col + 1] : 0.f;
            if (r0 < M) {
                C[(size_t)r0 * N + col]     = c[mi][ni][0] + b0;
                C[(size_t)r0 * N + col + 1] = c[mi][ni][1] + b1;
            }
            if (r0 + 8 < M) {
                C[(size_t)(r0 + 8) * N + col]     = c[mi][ni][2] + b0;
                C[(size_t)(r0 + 8) * N + col + 1] = c[mi][ni][3] + b1;
            }
        }
    }
}

// ---------------- attention coefficients al, ar -------------------------------
__global__ void attn_coef(const float* __restrict__ H, const float* __restrict__ a_src,
                          const float* __restrict__ a_dst, float* AL, float* AR,
                          int N, int C) {
    int warp = (blockIdx.x * blockDim.x + threadIdx.x) >> 5;
    int lane = threadIdx.x & 31;
    if (warp >= N * HEADS) return;
    int n = warp / HEADS, h = warp % HEADS;
    const float* hv = H + ((size_t)n * HEADS + h) * C;
    float sl = 0.f, sr = 0.f;
    for (int c = lane; c < C; c += 32) {
        float x = hv[c];
        sl += x * a_src[h * C + c];
        sr += x * a_dst[h * C + c];
    }
#pragma unroll
    for (int o = 16; o; o >>= 1) {
        sl += __shfl_down_sync(0xffffffffu, sl, o);
        sr += __shfl_down_sync(0xffffffffu, sr, o);
    }
    if (!lane) { AL[n * HEADS + h] = sl; AR[n * HEADS + h] = sr; }
}

// ---------------- fused GAT: softmax + gather-aggregate + ELU + LN ------------
// blockDim = 256 (8 warps = 8 heads). W = WPT*256, C = WPT*32.
template <int WPT, bool CONCAT>
__global__ void fused_gat_kernel(const float* __restrict__ H,
                                 const float* __restrict__ AL, const float* __restrict__ AR,
                                 const int* __restrict__ rowptr, const int* __restrict__ csrc,
                                 const float* __restrict__ b, const float* __restrict__ ls,
                                 const float* __restrict__ lb, float* __restrict__ X) {
    constexpr int W = WPT * 256;
    constexpr int C = WPT * 32;
    const int d = blockIdx.x;
    const int tid = threadIdx.x;
    const int lane = tid & 31;
    const int h = tid >> 5;

    const int beg = rowptr[d];
    const int deg = rowptr[d + 1] - beg;

    // ---- per-head softmax stats (warp h owns head h) ----
    const float ard = AR[d * HEADS + h];
    float selfl = AL[d * HEADS + h] + ard;
    selfl = selfl > 0.f ? selfl : 0.2f * selfl;
    float m = selfl;
    for (int i = lane; i < deg; i += 32) {
        int s = csrc[beg + i];
        float v = AL[s * HEADS + h] + ard;
        v = v > 0.f ? v : 0.2f * v;
        m = fmaxf(m, v);
    }
#pragma unroll
    for (int o = 16; o; o >>= 1) m = fmaxf(m, __shfl_xor_sync(0xffffffffu, m, o));
    // self-loop term contributed by lane 0 ONLY
    float ssum = (lane == 0) ? __expf(selfl - m) : 0.f;
    for (int i = lane; i < deg; i += 32) {
        int s = csrc[beg + i];
        float v = AL[s * HEADS + h] + ard;
        v = v > 0.f ? v : 0.2f * v;
        ssum += __expf(v - m);
    }
#pragma unroll
    for (int o = 16; o; o >>= 1) ssum += __shfl_xor_sync(0xffffffffu, ssum, o);
    const float inv = 1.f / ssum;

    __shared__ float alself[HEADS];
    __shared__ float wsh[256][HEADS];
    __shared__ int ssrc[256];
    if (!lane) alself[h] = __expf(selfl - m) * inv;
    __syncthreads();

    // ---- accumulate: self-loop first ----
    float acc[WPT];
    {
        const float* hd = H + (size_t)d * W;
#pragma unroll
        for (int j = 0; j < WPT; j++) {
            int col = j * 256 + tid;
            acc[j] = alself[col / C] * hd[col];
        }
    }

    // ---- gather over incoming edges (chunks of 256) ----
    for (int base = 0; base < deg; base += 256) {
        int n = min(256, deg - base);
        for (int i = lane; i < n; i += 32) {
            int s = csrc[beg + base + i];
            if (h == 0) ssrc[i] = s;
            float v = AL[s * HEADS + h] + ard;
            v = v > 0.f ? v : 0.2f * v;
            wsh[i][h] = __expf(v - m) * inv;
        }
        __syncthreads();
        for (int i = 0; i < n; i++) {
            const float* hs = H + (size_t)ssrc[i] * W;
#pragma unroll
            for (int j = 0; j < WPT; j++) {
                int col = j * 256 + tid;
                acc[j] += wsh[i][col / C] * hs[col];
            }
        }
        __syncthreads();
    }

    // ---- fused epilogue ----
    __shared__ float sa[8], sb2[8];
    __shared__ float mu_sh, inv_sh;
    if (CONCAT) {
        float v[WPT];
        float s1 = 0.f, s2 = 0.f;
#pragma unroll
        for (int j = 0; j < WPT; j++) {
            int col = j * 256 + tid;
            float t = acc[j] + b[col];
            t = t > 0.f ? t : (__expf(t) - 1.f);
            v[j] = t;
            s1 += t; s2 += t * t;
        }
#pragma unroll
        for (int o = 16; o; o >>= 1) {
            s1 += __shfl_down_sync(0xffffffffu, s1, o);
            s2 += __shfl_down_sync(0xffffffffu, s2, o);
        }
        if (!lane) { sa[h] = s1; sb2[h] = s2; }
        __syncthreads();
        if (tid == 0) {
            float t1 = 0.f, t2 = 0.f;
#pragma unroll
            for (int w = 0; w < 8; w++) { t1 += sa[w]; t2 += sb2[w]; }
            float mu = t1 / W;
            float var = t2 / W - mu * mu;
            mu_sh = mu; inv_sh = rsqrtf(var + LN_EPS);
        }
        __syncthreads();
        float mu = mu_sh, istd = inv_sh;
#pragma unroll
        for (int j = 0; j < WPT; j++) {
            int col = j * 256 + tid;
            X[(size_t)d * W + col] = (v[j] - mu) * istd * ls[col] + lb[col];
        }
    } else {
        // mean over heads -> C values, then ELU + LN over C
        __shared__ float arr[W];
#pragma unroll
        for (int j = 0; j < WPT; j++) arr[j * 256 + tid] = acc[j];
        __syncthreads();
        if (tid < C) {
            float t = 0.f;
#pragma unroll
            for (int hh = 0; hh < HEADS; hh++) t += arr[hh * C + tid];
            t = t * (1.f / HEADS) + b[tid];
            t = t > 0.f ? t : (__expf(t) - 1.f);
            float s1 = t, s2 = t * t;
#pragma unroll
            for (int o = 16; o; o >>= 1) {
                s1 += __shfl_xor_sync(0xffffffffu, s1, o);
                s2 += __shfl_xor_sync(0xffffffffu, s2, o);
            }
            if (!lane) { sa[tid >> 5] = s1; sb2[tid >> 5] = s2; }
        }
        __syncthreads();
        if (tid < C) {
            float T1 = 0.f, T2 = 0.f;
#pragma unroll
            for (int w = 0; w < C / 32; w++) { T1 += sa[w]; T2 += sb2[w]; }
            float mu = T1 / C;
            float var = T2 / C - mu * mu;
            float istd = rsqrtf(var + LN_EPS);
            float t = 0.f;
#pragma unroll
            for (int hh = 0; hh < HEADS; hh++) t += arr[hh * C + tid];
            t = t * (1.f / HEADS) + b[tid];
            t = t > 0.f ? t : (__expf(t) - 1.f);
            X[(size_t)d * C + tid] = (t - mu) * istd * ls[tid] + lb[tid];
        }
    }
}

// ---------------- projection epilogue: LN then exact GELU ---------------------
__global__ void ln_gelu(const float* __restrict__ IN, const float* __restrict__ ls,
                        const float* __restrict__ lb, float* node_out, int ld) {
    int n = blockIdx.x;
    int i = threadIdx.x;  // blockDim = 256 = ld
    float v = IN[(size_t)n * ld + i];
    __shared__ float sa[8], sb[8];
    __shared__ float mu_sh, inv_sh;
    float s1 = v, s2 = v * v;
    int lane = threadIdx.x & 31, wid = threadIdx.x >> 5;
#pragma unroll
    for (int o = 16; o; o >>= 1) {
        s1 += __shfl_down_sync(0xffffffffu, s1, o);
        s2 += __shfl_down_sync(0xffffffffu, s2, o);
    }
    if (!lane) { sa[wid] = s1; sb[wid] = s2; }
    __syncthreads();
    if (threadIdx.x == 0) {
        float t1 = 0.f, t2 = 0.f;
        for (int w = 0; w < 8; w++) { t1 += sa[w]; t2 += sb[w]; }
        float mu = t1 / ld;
        float var = t2 / ld - mu * mu;
        mu_sh = mu; inv_sh = rsqrtf(var + LN_EPS);
    }
    __syncthreads();
    float y = (v - mu_sh) * inv_sh * ls[i] + lb[i];
    float g = 0.5f * y * (1.f + erff(y * 0.70710678118654752f));
    node_out[(size_t)n * ld + i] = g;
}

// ---------------- pooling ------------------------------------------------------
__global__ void compute_q(const float* __restrict__ node_out, const float* __restrict__ wq,
                          const float* __restrict__ bq, float* q, int N) {
    int warp = (blockIdx.x * blockDim.x + threadIdx.x) >> 5;
    int lane = threadIdx.x & 31;
    if (warp >= N) return;
    const float* v = node_out + (size_t)warp * 256;
    float s = 0.f;
    for (int c = lane; c < 256; c += 32) s += v[c] * wq[c];
#pragma unroll
    for (int o = 16; o; o >>= 1) s += __shfl_down_sync(0xffffffffu, s, o);
    if (!lane) q[warp] = s + bq[0];
}

__global__ void softmax_reduce(const float* __restrict__ q, float* red, int N) {
    __shared__ float sh[32];
    int tid = threadIdx.x;
    float m = -INFINITY;
    for (int i = tid; i < N; i += blockDim.x) m = fmaxf(m, q[i]);
    int lane = tid & 31, wid = tid >> 5;
#pragma unroll
    for (int o = 16; o; o >>= 1) m = fmaxf(m, __shfl_down_sync(0xffffffffu, m, o));
    if (!lane) sh[wid] = m;
    __syncthreads();
    if (tid == 0) {
        float mm = -INFINITY;
        for (int w = 0; w < (int)(blockDim.x >> 5); w++) mm = fmaxf(mm, sh[w]);
        sh[0] = mm;
    }
    __syncthreads();
    float M = sh[0];
    __syncthreads();
    float s = 0.f;
    for (int i = tid; i < N; i += blockDim.x) s += __expf(q[i] - M);
#pragma unroll
    for (int o = 16; o; o >>= 1) s += __shfl_down_sync(0xffffffffu, s, o);
    if (!lane) sh[wid] = s;
    __syncthreads();
    if (tid == 0) {
        float ss = 0.f;
        for (int w = 0; w < (int)(blockDim.x >> 5); w++) ss += sh[w];
        red[0] = M; red[1] = ss;
    }
}

// one block per graph; nodes of graph b are [b*nper, (b+1)*nper)
__global__ void pool_kernel(const float* __restrict__ node_out, const float* __restrict__ q,
                            const float* __restrict__ red, float* out, int nper) {
    int b = blockIdx.x;
    int c = threadIdx.x;  // 256
    float M = red[0], S = red[1];
    float num = 0.f, den = 0.f;
    for (int i = 0; i < nper; i++) {
        int n = b * nper + i;
        float w = __expf(q[n] - M) / S;
        num += w * node_out[(size_t)n * 256 + c];
        den += w;
    }
    out[b * 256 + c] = num / fmaxf(den, 1e-8f);
}

// ---------------- launch -------------------------------------------------------
extern "C" void kernel_launch(void* const* d_in, const int* in_sizes, int n_in,
                              void* d_out, int out_size) {
    const float* xin = (const float*)d_in[0];
    const int* src = (const int*)d_in[1];
    const int* dst = (const int*)d_in[2];
    int E = in_sizes[1];
    int N = in_sizes[3];
    int B = out_size / 256 - N;
    float* out = (float*)d_out;
    float* graph_out = out;
    float* node_out = out + (size_t)B * 256;

    float *gH, *gX, *gP, *gAL, *gAR, *gQ, *gRED;
    int *gDEG, *gROW, *gCUR, *gCSRC;
    cudaGetSymbolAddress((void**)&gH, g_H);
    cudaGetSymbolAddress((void**)&gX, g_X);
    cudaGetSymbolAddress((void**)&gP, g_P);
    cudaGetSymbolAddress((void**)&gAL, g_AL);
    cudaGetSymbolAddress((void**)&gAR, g_AR);
    cudaGetSymbolAddress((void**)&gQ, g_Q);
    cudaGetSymbolAddress((void**)&gRED, g_RED);
    cudaGetSymbolAddress((void**)&gDEG, g_DEG);
    cudaGetSymbolAddress((void**)&gROW, g_ROW);
    cudaGetSymbolAddress((void**)&gCUR, g_CUR);
    cudaGetSymbolAddress((void**)&gCSRC, g_CSRC);

    // ---- CSR by destination ----
    zero_int<<<(N + 255) / 256, 256>>>(gDEG, N);
    deg_count<<<(E + 255) / 256, 256>>>(dst, gDEG, E);
    scan_kernel<<<1, 1024>>>(gDEG, gROW, gCUR, N);
    scatter_kernel<<<(E + 255) / 256, 256>>>(src, dst, gCUR, gCSRC, E);

    const float* x = xin;
    int K = in_sizes[0] / N;

    for (int l = 0; l < 3; l++) {
        int wi = 4 + 6 * l;
        const float* W  = (const float*)d_in[wi];
        const float* b  = (const float*)d_in[wi + 1];
        const float* as_ = (const float*)d_in[wi + 2];
        const float* ad  = (const float*)d_in[wi + 3];
        const float* ls = (const float*)d_in[wi + 4];
        const float* lb = (const float*)d_in[wi + 5];
        int C = in_sizes[wi + 2] / HEADS;
        int wdim = C * HEADS;

        dim3 ggrid(wdim / TBN, (N + TBM - 1) / TBM);
        gemm_tf32_kernel<<<ggrid, 256>>>(x, W, nullptr, gH, N, wdim, K);

        attn_coef<<<(N * HEADS * 32 + 255) / 256, 256>>>(gH, as_, ad, gAL, gAR, N, C);

        if (l == 0)
            fused_gat_kernel<8, true><<<N, 256>>>(gH, gAL, gAR, gROW, gCSRC, b, ls, lb, gX);
        else if (l == 1)
            fused_gat_kernel<4, true><<<N, 256>>>(gH, gAL, gAR, gROW, gCSRC, b, ls, lb, gX);
        else
            fused_gat_kernel<2, false><<<N, 256>>>(gH, gAL, gAR, gROW, gCSRC, b, ls, lb, gX);

        K = (l < 2) ? wdim : C;
        x = gX;
    }

    const float* wp = (const float*)d_in[22];
    const float* bp = (const float*)d_in[23];
    const float* lsp = (const float*)d_in[24];
    const float* lbp = (const float*)d_in[25];
    const float* wq = (const float*)d_in[26];
    const float* bq = (const float*)d_in[27];

    dim3 pgrid(256 / TBN, (N + TBM - 1) / TBM);
    gemm_tf32_kernel<<<pgrid, 256>>>(x, wp, bp, gP, N, 256, K);
    ln_gelu<<<N, 256>>>(gP, lsp, lbp, node_out, 256);

    compute_q<<<(N * 32 + 255) / 256, 256>>>(node_out, wq, bq, gQ, N);
    softmax_reduce<<<1, 1024>>>(gQ, gRED, N);
    pool_kernel<<<B, 256>>>(node_out, gQ, gRED, graph_out, N / B);
}

// round 12
// speedup vs baseline: 1.6800x; 1.6800x over previous
#include <cuda_runtime.h>
#include <cstdint>
#include <math.h>

#define HEADS 8
#define MAXN 4096
#define MAXW 2048
#define MAXEP 65536
#define LN_EPS 1e-5f

// ---------------- scratch (static device memory; no runtime alloc) -------------
__device__ float g_H[(size_t)MAXN * MAXW];     // h = x @ W
__device__ float g_X[(size_t)MAXN * MAXW];     // layer activations
__device__ float g_P[(size_t)MAXN * 256];      // projection out
__device__ float g_AL[MAXN * HEADS];
__device__ float g_AR[MAXN * HEADS];
__device__ float g_Q[MAXN];
__device__ float g_RED[2];
__device__ int   g_DEG[MAXN];
__device__ int   g_ROW[MAXN + 1];
__device__ int   g_CUR[MAXN];
__device__ int   g_CSRC[MAXEP];

// ---------------- CSR build ----------------------------------------------------
__global__ void zero_int(int* p, int n) {
    int i = blockIdx.x * blockDim.x + threadIdx.x;
    if (i < n) p[i] = 0;
}
__global__ void deg_count(const int* __restrict__ dst, int* deg, int E) {
    int i = blockIdx.x * blockDim.x + threadIdx.x;
    if (i < E) atomicAdd(&deg[dst[i]], 1);
}
// single-block exclusive scan over N<=4096 (1024 threads x 4 elems)
__global__ void scan_kernel(const int* __restrict__ deg, int* rowptr, int* cursor, int N) {
    __shared__ int sh[1024];
    int tid = threadIdx.x;
    int start = tid * 4;
    int local[4];
    int sum = 0;
#pragma unroll
    for (int i = 0; i < 4; i++) {
        int idx = start + i;
        local[i] = (idx < N) ? deg[idx] : 0;
        sum += local[i];
    }
    sh[tid] = sum;
    __syncthreads();
    for (int off = 1; off < 1024; off <<= 1) {
        int v = (tid >= off) ? sh[tid - off] : 0;
        __syncthreads();
        sh[tid] += v;
        __syncthreads();
    }
    int run = sh[tid] - sum;  // exclusive
#pragma unroll
    for (int i = 0; i < 4; i++) {
        int idx = start + i;
        if (idx < N) { rowptr[idx] = run; cursor[idx] = run; run += local[i]; }
    }
    if (tid == 1023) rowptr[N] = sh[1023];
}
__global__ void scatter_kernel(const int* __restrict__ src, const int* __restrict__ dst,
                               int* cursor, int* csrc, int E) {
    int i = blockIdx.x * blockDim.x + threadIdx.x;
    if (i < E) {
        int pos = atomicAdd(&cursor[dst[i]], 1);
        csrc[pos] = src[i];
    }
}

// ---------------- tf32 GEMM v3: 128x64x32, 3-stage cp.async pipeline ----------
// 256 threads = 8 warps (4m x 2n), warp tile 32x32 = 2(m16) x 4(n8) frags.
#define BM 128
#define BN 64
#define BK 32
#define ASTR 36       // fp32 smem; frag bank = 4*gid + tig = lane  -> conflict-free
#define BSTR 72       // frag bank = 8*tig + gid                    -> conflict-free
#define NSTAGE 3
#define A_STAGE (BM * ASTR)
#define B_STAGE (BK * BSTR)
#define GEMM_SMEM ((NSTAGE * (A_STAGE + B_STAGE)) * 4)

__device__ __forceinline__ unsigned f2tf32(float x) {
    unsigned r;
    asm("cvt.rna.tf32.f32 %0, %1;" : "=r"(r) : "f"(x));
    return r;
}

__device__ __forceinline__ void gemm_issue_tile(
    const float* __restrict__ A, const float* __restrict__ B,
    int M, int K, int N, int rowBase, int colBase, int kt,
    uint32_t As_u, uint32_t Bs_u, int s, int tid)
{
    const uint32_t a_base = As_u + (uint32_t)(s * A_STAGE) * 4u;
    const uint32_t b_base = Bs_u + (uint32_t)(s * B_STAGE) * 4u;
    const int k0 = kt * BK;
#pragma unroll
    for (int p = 0; p < 4; p++) {
        int i = tid + p * 256;
        int r = i >> 3, c = (i & 7) << 2;
        const float* g = &A[(size_t)(rowBase + r) * K + k0 + c];
        int sz = (rowBase + r < M) ? 16 : 0;
        asm volatile("cp.async.cg.shared.global [%0], [%1], 16, %2;"
                     :: "r"(a_base + (uint32_t)(r * ASTR + c) * 4u), "l"(g), "r"(sz));
    }
#pragma unroll
    for (int p = 0; p < 2; p++) {
        int i = tid + p * 256;
        int r = i >> 4, c = (i & 15) << 2;
        const float* g = &B[(size_t)(k0 + r) * N + colBase + c];
        asm volatile("cp.async.cg.shared.global [%0], [%1], 16;"
                     :: "r"(b_base + (uint32_t)(r * BSTR + c) * 4u), "l"(g));
    }
    asm volatile("cp.async.commit_group;");
}

__global__ void __launch_bounds__(256, 1)
gemm_tf32_kernel(const float* __restrict__ A, const float* __restrict__ B,
                 const float* __restrict__ bias, float* __restrict__ C,
                 int M, int N, int K) {
    extern __shared__ float sm[];
    float* As = sm;
    float* Bs = sm + NSTAGE * A_STAGE;
    const uint32_t As_u = (uint32_t)__cvta_generic_to_shared(As);
    const uint32_t Bs_u = (uint32_t)__cvta_generic_to_shared(Bs);

    const int tid = threadIdx.x;
    const int warp = tid >> 5, lane = tid & 31;
    const int wm = warp >> 1, wn = warp & 1;
    const int gid = lane >> 2, tig = lane & 3;
    const int rowBase = blockIdx.y * BM;
    const int colBase = blockIdx.x * BN;
    const int nk = K / BK;

    float c[2][4][4];
#pragma unroll
    for (int mi = 0; mi < 2; mi++)
#pragma unroll
        for (int ni = 0; ni < 4; ni++)
#pragma unroll
            for (int f = 0; f < 4; f++) c[mi][ni][f] = 0.f;

    // ---- prologue: issue up to NSTAGE-1 tiles ahead ----
    int issued = 0;
#pragma unroll
    for (int s = 0; s < NSTAGE - 1; s++)
        if (issued < nk) { gemm_issue_tile(A, B, M, K, N, rowBase, colBase, issued, As_u, Bs_u, issued % NSTAGE, tid); issued++; }

    for (int t = 0; t < nk; t++) {
        // tile t must be complete; allowed pending = issued - (t+1) in {0,1}
        if (issued - t - 1 > 0) asm volatile("cp.async.wait_group 1;");
        else                    asm volatile("cp.async.wait_group 0;");
        __syncthreads();

        const float* Ac = As + (t % NSTAGE) * A_STAGE;
        const float* Bc = Bs + (t % NSTAGE) * B_STAGE;

#pragma unroll
        for (int ks = 0; ks < BK; ks += 8) {
            unsigned a[2][4], b[4][2];
#pragma unroll
            for (int mi = 0; mi < 2; mi++) {
                int mb = wm * 32 + mi * 16;
                a[mi][0] = f2tf32(Ac[(mb + gid) * ASTR + ks + tig]);
                a[mi][1] = f2tf32(Ac[(mb + gid + 8) * ASTR + ks + tig]);
                a[mi][2] = f2tf32(Ac[(mb + gid) * ASTR + ks + tig + 4]);
                a[mi][3] = f2tf32(Ac[(mb + gid + 8) * ASTR + ks + tig + 4]);
            }
#pragma unroll
            for (int ni = 0; ni < 4; ni++) {
                int nb = wn * 32 + ni * 8;
                b[ni][0] = f2tf32(Bc[(ks + tig) * BSTR + nb + gid]);
                b[ni][1] = f2tf32(Bc[(ks + tig + 4) * BSTR + nb + gid]);
            }
#pragma unroll
            for (int mi = 0; mi < 2; mi++)
#pragma unroll
                for (int ni = 0; ni < 4; ni++) {
                    asm volatile(
                        "mma.sync.aligned.m16n8k8.row.col.f32.tf32.tf32.f32 "
                        "{%0,%1,%2,%3}, {%4,%5,%6,%7}, {%8,%9}, {%0,%1,%2,%3};"
                        : "+f"(c[mi][ni][0]), "+f"(c[mi][ni][1]),
                          "+f"(c[mi][ni][2]), "+f"(c[mi][ni][3])
                        : "r"(a[mi][0]), "r"(a[mi][1]), "r"(a[mi][2]), "r"(a[mi][3]),
                          "r"(b[ni][0]), "r"(b[ni][1]));
                }
        }
        __syncthreads();   // finished reading stage t before it is overwritten

        if (issued < nk) { gemm_issue_tile(A, B, M, K, N, rowBase, colBase, issued, As_u, Bs_u, issued % NSTAGE, tid); issued++; }
    }

    // ---- store ----
#pragma unroll
    for (int mi = 0; mi < 2; mi++) {
        int r0 = rowBase + wm * 32 + mi * 16 + gid;
#pragma unroll
        for (int ni = 0; ni < 4; ni++) {
            int col = colBase + wn * 32 + ni * 8 + tig * 2;
            float b0 = bias ? bias[col] : 0.f;
            float b1 = bias ? bias[col + 1] : 0.f;
            if (r0 < M) {
                C[(size_t)r0 * N + col]     = c[mi][ni][0] + b0;
                C[(size_t)r0 * N + col + 1] = c[mi][ni][1] + b1;
            }
            if (r0 + 8 < M) {
                C[(size_t)(r0 + 8) * N + col]     = c[mi][ni][2] + b0;
                C[(size_t)(r0 + 8) * N + col + 1] = c[mi][ni][3] + b1;
            }
        }
    }
}

// ---------------- attention coefficients al, ar -------------------------------
__global__ void attn_coef(const float* __restrict__ H, const float* __restrict__ a_src,
                          const float* __restrict__ a_dst, float* AL, float* AR,
                          int N, int C) {
    int warp = (blockIdx.x * blockDim.x + threadIdx.x) >> 5;
    int lane = threadIdx.x & 31;
    if (warp >= N * HEADS) return;
    int n = warp / HEADS, h = warp % HEADS;
    const float* hv = H + ((size_t)n * HEADS + h) * C;
    float sl = 0.f, sr = 0.f;
    for (int c = lane; c < C; c += 32) {
        float x = hv[c];
        sl += x * a_src[h * C + c];
        sr += x * a_dst[h * C + c];
    }
#pragma unroll
    for (int o = 16; o; o >>= 1) {
        sl += __shfl_down_sync(0xffffffffu, sl, o);
        sr += __shfl_down_sync(0xffffffffu, sr, o);
    }
    if (!lane) { AL[n * HEADS + h] = sl; AR[n * HEADS + h] = sr; }
}

// ---------------- fused GAT: softmax + gather-aggregate + ELU + LN ------------
// blockDim = 256 (8 warps = 8 heads). W = WPT*256, C = WPT*32.
template <int WPT, bool CONCAT>
__global__ void fused_gat_kernel(const float* __restrict__ H,
                                 const float* __restrict__ AL, const float* __restrict__ AR,
                                 const int* __restrict__ rowptr, const int* __restrict__ csrc,
                                 const float* __restrict__ b, const float* __restrict__ ls,
                                 const float* __restrict__ lb, float* __restrict__ X) {
    constexpr int W = WPT * 256;
    constexpr int C = WPT * 32;
    const int d = blockIdx.x;
    const int tid = threadIdx.x;
    const int lane = tid & 31;
    const int h = tid >> 5;

    const int beg = rowptr[d];
    const int deg = rowptr[d + 1] - beg;

    // ---- per-head softmax stats (warp h owns head h) ----
    const float ard = AR[d * HEADS + h];
    float selfl = AL[d * HEADS + h] + ard;
    selfl = selfl > 0.f ? selfl : 0.2f * selfl;
    float m = selfl;
    for (int i = lane; i < deg; i += 32) {
        int s = csrc[beg + i];
        float v = AL[s * HEADS + h] + ard;
        v = v > 0.f ? v : 0.2f * v;
        m = fmaxf(m, v);
    }
#pragma unroll
    for (int o = 16; o; o >>= 1) m = fmaxf(m, __shfl_xor_sync(0xffffffffu, m, o));
    // self-loop term contributed by lane 0 ONLY
    float ssum = (lane == 0) ? __expf(selfl - m) : 0.f;
    for (int i = lane; i < deg; i += 32) {
        int s = csrc[beg + i];
        float v = AL[s * HEADS + h] + ard;
        v = v > 0.f ? v : 0.2f * v;
        ssum += __expf(v - m);
    }
#pragma unroll
    for (int o = 16; o; o >>= 1) ssum += __shfl_xor_sync(0xffffffffu, ssum, o);
    const float inv = 1.f / ssum;

    __shared__ float alself[HEADS];
    __shared__ float wsh[256][HEADS];
    __shared__ int ssrc[256];
    if (!lane) alself[h] = __expf(selfl - m) * inv;
    __syncthreads();

    // ---- accumulate: self-loop first ----
    float acc[WPT];
    {
        const float* hd = H + (size_t)d * W;
#pragma unroll
        for (int j = 0; j < WPT; j++) {
            int col = j * 256 + tid;
            acc[j] = alself[col / C] * hd[col];
        }
    }

    // ---- gather over incoming edges (chunks of 256) ----
    for (int base = 0; base < deg; base += 256) {
        int n = min(256, deg - base);
        for (int i = lane; i < n; i += 32) {
            int s = csrc[beg + base + i];
            if (h == 0) ssrc[i] = s;
            float v = AL[s * HEADS + h] + ard;
            v = v > 0.f ? v : 0.2f * v;
            wsh[i][h] = __expf(v - m) * inv;
        }
        __syncthreads();
        for (int i = 0; i < n; i++) {
            const float* hs = H + (size_t)ssrc[i] * W;
#pragma unroll
            for (int j = 0; j < WPT; j++) {
                int col = j * 256 + tid;
                acc[j] += wsh[i][col / C] * hs[col];
            }
        }
        __syncthreads();
    }

    // ---- fused epilogue ----
    __shared__ float sa[8], sb2[8];
    __shared__ float mu_sh, inv_sh;
    if (CONCAT) {
        float v[WPT];
        float s1 = 0.f, s2 = 0.f;
#pragma unroll
        for (int j = 0; j < WPT; j++) {
            int col = j * 256 + tid;
            float t = acc[j] + b[col];
            t = t > 0.f ? t : (__expf(t) - 1.f);
            v[j] = t;
            s1 += t; s2 += t * t;
        }
#pragma unroll
        for (int o = 16; o; o >>= 1) {
            s1 += __shfl_down_sync(0xffffffffu, s1, o);
            s2 += __shfl_down_sync(0xffffffffu, s2, o);
        }
        if (!lane) { sa[h] = s1; sb2[h] = s2; }
        __syncthreads();
        if (tid == 0) {
            float t1 = 0.f, t2 = 0.f;
#pragma unroll
            for (int w = 0; w < 8; w++) { t1 += sa[w]; t2 += sb2[w]; }
            float mu = t1 / W;
            float var = t2 / W - mu * mu;
            mu_sh = mu; inv_sh = rsqrtf(var + LN_EPS);
        }
        __syncthreads();
        float mu = mu_sh, istd = inv_sh;
#pragma unroll
        for (int j = 0; j < WPT; j++) {
            int col = j * 256 + tid;
            X[(size_t)d * W + col] = (v[j] - mu) * istd * ls[col] + lb[col];
        }
    } else {
        // mean over heads -> C values, then ELU + LN over C
        __shared__ float arr[W];
#pragma unroll
        for (int j = 0; j < WPT; j++) arr[j * 256 + tid] = acc[j];
        __syncthreads();
        if (tid < C) {
            float t = 0.f;
#pragma unroll
            for (int hh = 0; hh < HEADS; hh++) t += arr[hh * C + tid];
            t = t * (1.f / HEADS) + b[tid];
            t = t > 0.f ? t : (__expf(t) - 1.f);
            float s1 = t, s2 = t * t;
#pragma unroll
            for (int o = 16; o; o >>= 1) {
                s1 += __shfl_xor_sync(0xffffffffu, s1, o);
                s2 += __shfl_xor_sync(0xffffffffu, s2, o);
            }
            if (!lane) { sa[tid >> 5] = s1; sb2[tid >> 5] = s2; }
        }
        __syncthreads();
        if (tid < C) {
            float T1 = 0.f, T2 = 0.f;
#pragma unroll
            for (int w = 0; w < C / 32; w++) { T1 += sa[w]; T2 += sb2[w]; }
            float mu = T1 / C;
            float var = T2 / C - mu * mu;
            float istd = rsqrtf(var + LN_EPS);
            float t = 0.f;
#pragma unroll
            for (int hh = 0; hh < HEADS; hh++) t += arr[hh * C + tid];
            t = t * (1.f / HEADS) + b[tid];
            t = t > 0.f ? t : (__expf(t) - 1.f);
            X[(size_t)d * C + tid] = (t - mu) * istd * ls[tid] + lb[tid];
        }
    }
}

// ---------------- projection epilogue: LN then exact GELU ---------------------
__global__ void ln_gelu(const float* __restrict__ IN, const float* __restrict__ ls,
                        const float* __restrict__ lb, float* node_out, int ld) {
    int n = blockIdx.x;
    int i = threadIdx.x;  // blockDim = 256 = ld
    float v = IN[(size_t)n * ld + i];
    __shared__ float sa[8], sb[8];
    __shared__ float mu_sh, inv_sh;
    float s1 = v, s2 = v * v;
    int lane = threadIdx.x & 31, wid = threadIdx.x >> 5;
#pragma unroll
    for (int o = 16; o; o >>= 1) {
        s1 += __shfl_down_sync(0xffffffffu, s1, o);
        s2 += __shfl_down_sync(0xffffffffu, s2, o);
    }
    if (!lane) { sa[wid] = s1; sb[wid] = s2; }
    __syncthreads();
    if (threadIdx.x == 0) {
        float t1 = 0.f, t2 = 0.f;
        for (int w = 0; w < 8; w++) { t1 += sa[w]; t2 += sb[w]; }
        float mu = t1 / ld;
        float var = t2 / ld - mu * mu;
        mu_sh = mu; inv_sh = rsqrtf(var + LN_EPS);
    }
    __syncthreads();
    float y = (v - mu_sh) * inv_sh * ls[i] + lb[i];
    float g = 0.5f * y * (1.f + erff(y * 0.70710678118654752f));
    node_out[(size_t)n * ld + i] = g;
}

// ---------------- pooling ------------------------------------------------------
__global__ void compute_q(const float* __restrict__ node_out, const float* __restrict__ wq,
                          const float* __restrict__ bq, float* q, int N) {
    int warp = (blockIdx.x * blockDim.x + threadIdx.x) >> 5;
    int lane = threadIdx.x & 31;
    if (warp >= N) return;
    const float* v = node_out + (size_t)warp * 256;
    float s = 0.f;
    for (int c = lane; c < 256; c += 32) s += v[c] * wq[c];
#pragma unroll
    for (int o = 16; o; o >>= 1) s += __shfl_down_sync(0xffffffffu, s, o);
    if (!lane) q[warp] = s + bq[0];
}

__global__ void softmax_reduce(const float* __restrict__ q, float* red, int N) {
    __shared__ float sh[32];
    int tid = threadIdx.x;
    float m = -INFINITY;
    for (int i = tid; i < N; i += blockDim.x) m = fmaxf(m, q[i]);
    int lane = tid & 31, wid = tid >> 5;
#pragma unroll
    for (int o = 16; o; o >>= 1) m = fmaxf(m, __shfl_down_sync(0xffffffffu, m, o));
    if (!lane) sh[wid] = m;
    __syncthreads();
    if (tid == 0) {
        float mm = -INFINITY;
        for (int w = 0; w < (int)(blockDim.x >> 5); w++) mm = fmaxf(mm, sh[w]);
        sh[0] = mm;
    }
    __syncthreads();
    float M = sh[0];
    __syncthreads();
    float s = 0.f;
    for (int i = tid; i < N; i += blockDim.x) s += __expf(q[i] - M);
#pragma unroll
    for (int o = 16; o; o >>= 1) s += __shfl_down_sync(0xffffffffu, s, o);
    if (!lane) sh[wid] = s;
    __syncthreads();
    if (tid == 0) {
        float ss = 0.f;
        for (int w = 0; w < (int)(blockDim.x >> 5); w++) ss += sh[w];
        red[0] = M; red[1] = ss;
    }
}

// one block per graph; nodes of graph b are [b*nper, (b+1)*nper)
__global__ void pool_kernel(const float* __restrict__ node_out, const float* __restrict__ q,
                            const float* __restrict__ red, float* out, int nper) {
    int b = blockIdx.x;
    int c = threadIdx.x;  // 256
    float M = red[0], S = red[1];
    float num = 0.f, den = 0.f;
    for (int i = 0; i < nper; i++) {
        int n = b * nper + i;
        float w = __expf(q[n] - M) / S;
        num += w * node_out[(size_t)n * 256 + c];
        den += w;
    }
    out[b * 256 + c] = num / fmaxf(den, 1e-8f);
}

// ---------------- launch -------------------------------------------------------
extern "C" void kernel_launch(void* const* d_in, const int* in_sizes, int n_in,
                              void* d_out, int out_size) {
    const float* xin = (const float*)d_in[0];
    const int* src = (const int*)d_in[1];
    const int* dst = (const int*)d_in[2];
    int E = in_sizes[1];
    int N = in_sizes[3];
    int B = out_size / 256 - N;
    float* out = (float*)d_out;
    float* graph_out = out;
    float* node_out = out + (size_t)B * 256;

    float *gH, *gX, *gP, *gAL, *gAR, *gQ, *gRED;
    int *gDEG, *gROW, *gCUR, *gCSRC;
    cudaGetSymbolAddress((void**)&gH, g_H);
    cudaGetSymbolAddress((void**)&gX, g_X);
    cudaGetSymbolAddress((void**)&gP, g_P);
    cudaGetSymbolAddress((void**)&gAL, g_AL);
    cudaGetSymbolAddress((void**)&gAR, g_AR);
    cudaGetSymbolAddress((void**)&gQ, g_Q);
    cudaGetSymbolAddress((void**)&gRED, g_RED);
    cudaGetSymbolAddress((void**)&gDEG, g_DEG);
    cudaGetSymbolAddress((void**)&gROW, g_ROW);
    cudaGetSymbolAddress((void**)&gCUR, g_CUR);
    cudaGetSymbolAddress((void**)&gCSRC, g_CSRC);

    cudaFuncSetAttribute(gemm_tf32_kernel,
                         cudaFuncAttributeMaxDynamicSharedMemorySize, GEMM_SMEM);

    // ---- CSR by destination ----
    zero_int<<<(N + 255) / 256, 256>>>(gDEG, N);
    deg_count<<<(E + 255) / 256, 256>>>(dst, gDEG, E);
    scan_kernel<<<1, 1024>>>(gDEG, gROW, gCUR, N);
    scatter_kernel<<<(E + 255) / 256, 256>>>(src, dst, gCUR, gCSRC, E);

    const float* x = xin;
    int K = in_sizes[0] / N;

    for (int l = 0; l < 3; l++) {
        int wi = 4 + 6 * l;
        const float* W  = (const float*)d_in[wi];
        const float* b  = (const float*)d_in[wi + 1];
        const float* as_ = (const float*)d_in[wi + 2];
        const float* ad  = (const float*)d_in[wi + 3];
        const float* ls = (const float*)d_in[wi + 4];
        const float* lb = (const float*)d_in[wi + 5];
        int C = in_sizes[wi + 2] / HEADS;
        int wdim = C * HEADS;

        dim3 ggrid(wdim / BN, (N + BM - 1) / BM);
        gemm_tf32_kernel<<<ggrid, 256, GEMM_SMEM>>>(x, W, nullptr, gH, N, wdim, K);

        attn_coef<<<(N * HEADS * 32 + 255) / 256, 256>>>(gH, as_, ad, gAL, gAR, N, C);

        if (l == 0)
            fused_gat_kernel<8, true><<<N, 256>>>(gH, gAL, gAR, gROW, gCSRC, b, ls, lb, gX);
        else if (l == 1)
            fused_gat_kernel<4, true><<<N, 256>>>(gH, gAL, gAR, gROW, gCSRC, b, ls, lb, gX);
        else
            fused_gat_kernel<2, false><<<N, 256>>>(gH, gAL, gAR, gROW, gCSRC, b, ls, lb, gX);

        K = (l < 2) ? wdim : C;
        x = gX;
    }

    const float* wp = (const float*)d_in[22];
    const float* bp = (const float*)d_in[23];
    const float* lsp = (const float*)d_in[24];
    const float* lbp = (const float*)d_in[25];
    const float* wq = (const float*)d_in[26];
    const float* bq = (const float*)d_in[27];

    dim3 pgrid(256 / BN, (N + BM - 1) / BM);
    gemm_tf32_kernel<<<pgrid, 256, GEMM_SMEM>>>(x, wp, bp, gP, N, 256, K);
    ln_gelu<<<N, 256>>>(gP, lsp, lbp, node_out, 256);

    compute_q<<<(N * 32 + 255) / 256, 256>>>(node_out, wq, bq, gQ, N);
    softmax_reduce<<<1, 1024>>>(gQ, gRED, N);
    pool_kernel<<<B, 256>>>(node_out, gQ, gRED, graph_out, N / B);
}

// round 14
// speedup vs baseline: 1.7764x; 1.0573x over previous
#include <cuda_runtime.h>
#include <cstdint>
#include <math.h>

#define HEADS 8
#define MAXN 4096
#define MAXW 2048
#define MAXEP 65536
#define LN_EPS 1e-5f

// ---------------- scratch (static device memory; no runtime alloc) -------------
__device__ float g_H[(size_t)MAXN * MAXW];     // h = x @ W
__device__ float g_X[(size_t)MAXN * MAXW];     // layer activations
__device__ float g_P[(size_t)MAXN * 256];      // projection out
__device__ float g_AL[MAXN * HEADS];
__device__ float g_AR[MAXN * HEADS];
__device__ float g_Q[MAXN];
__device__ float g_RED[2];
__device__ int   g_DEG[MAXN];
__device__ int   g_ROW[MAXN + 1];
__device__ int   g_CUR[MAXN];
__device__ int   g_CSRC[MAXEP];

// ---------------- CSR build ----------------------------------------------------
__global__ void zero_int(int* p, int n) {
    int i = blockIdx.x * blockDim.x + threadIdx.x;
    if (i < n) p[i] = 0;
}
__global__ void deg_count(const int* __restrict__ dst, int* deg, int E) {
    int i = blockIdx.x * blockDim.x + threadIdx.x;
    if (i < E) atomicAdd(&deg[dst[i]], 1);
}
// single-block exclusive scan over N<=4096 (1024 threads x 4 elems)
__global__ void scan_kernel(const int* __restrict__ deg, int* rowptr, int* cursor, int N) {
    __shared__ int sh[1024];
    int tid = threadIdx.x;
    int start = tid * 4;
    int local[4];
    int sum = 0;
#pragma unroll
    for (int i = 0; i < 4; i++) {
        int idx = start + i;
        local[i] = (idx < N) ? deg[idx] : 0;
        sum += local[i];
    }
    sh[tid] = sum;
    __syncthreads();
    for (int off = 1; off < 1024; off <<= 1) {
        int v = (tid >= off) ? sh[tid - off] : 0;
        __syncthreads();
        sh[tid] += v;
        __syncthreads();
    }
    int run = sh[tid] - sum;  // exclusive
#pragma unroll
    for (int i = 0; i < 4; i++) {
        int idx = start + i;
        if (idx < N) { rowptr[idx] = run; cursor[idx] = run; run += local[i]; }
    }
    if (tid == 1023) rowptr[N] = sh[1023];
}
__global__ void scatter_kernel(const int* __restrict__ src, const int* __restrict__ dst,
                               int* cursor, int* csrc, int E) {
    int i = blockIdx.x * blockDim.x + threadIdx.x;
    if (i < E) {
        int pos = atomicAdd(&cursor[dst[i]], 1);
        csrc[pos] = src[i];
    }
}

// ---------------- tf32 GEMM v3: 128x64x32, 3-stage cp.async pipeline ----------
// 256 threads = 8 warps (4m x 2n), warp tile 32x32 = 2(m16) x 4(n8) frags.
#define BM 128
#define BN 64
#define BK 32
#define ASTR 36       // fp32 smem; frag bank = 4*gid + tig = lane  -> conflict-free
#define BSTR 72       // frag bank = 8*tig + gid                    -> conflict-free
#define NSTAGE 3
#define A_STAGE (BM * ASTR)
#define B_STAGE (BK * BSTR)
#define GEMM_SMEM ((NSTAGE * (A_STAGE + B_STAGE)) * 4)

__device__ __forceinline__ unsigned f2tf32(float x) {
    unsigned r;
    asm("cvt.rna.tf32.f32 %0, %1;" : "=r"(r) : "f"(x));
    return r;
}

__device__ __forceinline__ void gemm_issue_tile(
    const float* __restrict__ A, const float* __restrict__ B,
    int M, int K, int N, int rowBase, int colBase, int kt,
    uint32_t As_u, uint32_t Bs_u, int s, int tid)
{
    const uint32_t a_base = As_u + (uint32_t)(s * A_STAGE) * 4u;
    const uint32_t b_base = Bs_u + (uint32_t)(s * B_STAGE) * 4u;
    const int k0 = kt * BK;
#pragma unroll
    for (int p = 0; p < 4; p++) {
        int i = tid + p * 256;
        int r = i >> 3, c = (i & 7) << 2;
        const float* g = &A[(size_t)(rowBase + r) * K + k0 + c];
        int sz = (rowBase + r < M) ? 16 : 0;
        asm volatile("cp.async.cg.shared.global [%0], [%1], 16, %2;"
                     :: "r"(a_base + (uint32_t)(r * ASTR + c) * 4u), "l"(g), "r"(sz));
    }
#pragma unroll
    for (int p = 0; p < 2; p++) {
        int i = tid + p * 256;
        int r = i >> 4, c = (i & 15) << 2;
        const float* g = &B[(size_t)(k0 + r) * N + colBase + c];
        asm volatile("cp.async.cg.shared.global [%0], [%1], 16;"
                     :: "r"(b_base + (uint32_t)(r * BSTR + c) * 4u), "l"(g));
    }
    asm volatile("cp.async.commit_group;");
}

__global__ void __launch_bounds__(256, 1)
gemm_tf32_kernel(const float* __restrict__ A, const float* __restrict__ B,
                 const float* __restrict__ bias, float* __restrict__ C,
                 int M, int N, int K) {
    extern __shared__ float sm[];
    float* As = sm;
    float* Bs = sm + NSTAGE * A_STAGE;
    const uint32_t As_u = (uint32_t)__cvta_generic_to_shared(As);
    const uint32_t Bs_u = (uint32_t)__cvta_generic_to_shared(Bs);

    const int tid = threadIdx.x;
    const int warp = tid >> 5, lane = tid & 31;
    const int wm = warp >> 1, wn = warp & 1;
    const int gid = lane >> 2, tig = lane & 3;
    const int rowBase = blockIdx.y * BM;
    const int colBase = blockIdx.x * BN;
    const int nk = K / BK;

    float c[2][4][4];
#pragma unroll
    for (int mi = 0; mi < 2; mi++)
#pragma unroll
        for (int ni = 0; ni < 4; ni++)
#pragma unroll
            for (int f = 0; f < 4; f++) c[mi][ni][f] = 0.f;

    // ---- prologue: issue up to NSTAGE-1 tiles ahead ----
    int issued = 0;
#pragma unroll
    for (int s = 0; s < NSTAGE - 1; s++)
        if (issued < nk) { gemm_issue_tile(A, B, M, K, N, rowBase, colBase, issued, As_u, Bs_u, issued % NSTAGE, tid); issued++; }

    for (int t = 0; t < nk; t++) {
        // tile t must be complete; allowed pending = issued - (t+1) in {0,1}
        if (issued - t - 1 > 0) asm volatile("cp.async.wait_group 1;");
        else                    asm volatile("cp.async.wait_group 0;");
        __syncthreads();

        const float* Ac = As + (t % NSTAGE) * A_STAGE;
        const float* Bc = Bs + (t % NSTAGE) * B_STAGE;

#pragma unroll
        for (int ks = 0; ks < BK; ks += 8) {
            unsigned a[2][4], b[4][2];
#pragma unroll
            for (int mi = 0; mi < 2; mi++) {
                int mb = wm * 32 + mi * 16;
                a[mi][0] = f2tf32(Ac[(mb + gid) * ASTR + ks + tig]);
                a[mi][1] = f2tf32(Ac[(mb + gid + 8) * ASTR + ks + tig]);
                a[mi][2] = f2tf32(Ac[(mb + gid) * ASTR + ks + tig + 4]);
                a[mi][3] = f2tf32(Ac[(mb + gid + 8) * ASTR + ks + tig + 4]);
            }
#pragma unroll
            for (int ni = 0; ni < 4; ni++) {
                int nb = wn * 32 + ni * 8;
                b[ni][0] = f2tf32(Bc[(ks + tig) * BSTR + nb + gid]);
                b[ni][1] = f2tf32(Bc[(ks + tig + 4) * BSTR + nb + gid]);
            }
#pragma unroll
            for (int mi = 0; mi < 2; mi++)
#pragma unroll
                for (int ni = 0; ni < 4; ni++) {
                    asm volatile(
                        "mma.sync.aligned.m16n8k8.row.col.f32.tf32.tf32.f32 "
                        "{%0,%1,%2,%3}, {%4,%5,%6,%7}, {%8,%9}, {%0,%1,%2,%3};"
                        : "+f"(c[mi][ni][0]), "+f"(c[mi][ni][1]),
                          "+f"(c[mi][ni][2]), "+f"(c[mi][ni][3])
                        : "r"(a[mi][0]), "r"(a[mi][1]), "r"(a[mi][2]), "r"(a[mi][3]),
                          "r"(b[ni][0]), "r"(b[ni][1]));
                }
        }
        __syncthreads();   // finished reading stage t before it is overwritten

        if (issued < nk) { gemm_issue_tile(A, B, M, K, N, rowBase, colBase, issued, As_u, Bs_u, issued % NSTAGE, tid); issued++; }
    }

    // ---- store ----
#pragma unroll
    for (int mi = 0; mi < 2; mi++) {
        int r0 = rowBase + wm * 32 + mi * 16 + gid;
#pragma unroll
        for (int ni = 0; ni < 4; ni++) {
            int col = colBase + wn * 32 + ni * 8 + tig * 2;
            float b0 = bias ? bias[col] : 0.f;
            float b1 = bias ? bias[col + 1] : 0.f;
            if (r0 < M) {
                C[(size_t)r0 * N + col]     = c[mi][ni][0] + b0;
                C[(size_t)r0 * N + col + 1] = c[mi][ni][1] + b1;
            }
            if (r0 + 8 < M) {
                C[(size_t)(r0 + 8) * N + col]     = c[mi][ni][2] + b0;
                C[(size_t)(r0 + 8) * N + col + 1] = c[mi][ni][3] + b1;
            }
        }
    }
}

// ---------------- attention coefficients al, ar (float4) ----------------------
__global__ void attn_coef(const float* __restrict__ H, const float* __restrict__ a_src,
                          const float* __restrict__ a_dst, float* AL, float* AR,
                          int N, int C) {
    int warp = (blockIdx.x * blockDim.x + threadIdx.x) >> 5;
    int lane = threadIdx.x & 31;
    if (warp >= N * HEADS) return;
    int n = warp / HEADS, h = warp % HEADS;
    const float* hv = H + ((size_t)n * HEADS + h) * C;
    const float* asv = a_src + h * C;
    const float* adv = a_dst + h * C;
    float sl = 0.f, sr = 0.f;
    for (int c4 = lane; c4 < (C >> 2); c4 += 32) {
        float4 x = *(const float4*)&hv[c4 << 2];
        float4 s = *(const float4*)&asv[c4 << 2];
        float4 d = *(const float4*)&adv[c4 << 2];
        sl += x.x * s.x + x.y * s.y + x.z * s.z + x.w * s.w;
        sr += x.x * d.x + x.y * d.y + x.z * d.z + x.w * d.w;
    }
#pragma unroll
    for (int o = 16; o; o >>= 1) {
        sl += __shfl_down_sync(0xffffffffu, sl, o);
        sr += __shfl_down_sync(0xffffffffu, sr, o);
    }
    if (!lane) { AL[n * HEADS + h] = sl; AR[n * HEADS + h] = sr; }
}

// ---------------- fused GAT: softmax + gather-aggregate + ELU + LN ------------
// blockDim = 256 (8 warps = 8 heads). W = WPT*256, C = WPT*32.
// VEC = 4 or 2: vector width of gather loads (element idx = (j*256+tid)*VEC + k)
template <int WPT, int VEC, bool CONCAT>
__global__ void fused_gat_kernel(const float* __restrict__ H,
                                 const float* __restrict__ AL, const float* __restrict__ AR,
                                 const int* __restrict__ rowptr, const int* __restrict__ csrc,
                                 const float* __restrict__ b, const float* __restrict__ ls,
                                 const float* __restrict__ lb, float* __restrict__ X) {
    constexpr int W = WPT * 256;
    constexpr int C = WPT * 32;
    constexpr int NV = WPT / VEC;   // vector loads per thread
    const int d = blockIdx.x;
    const int tid = threadIdx.x;
    const int lane = tid & 31;
    const int h = tid >> 5;

    const int beg = rowptr[d];
    const int deg = rowptr[d + 1] - beg;

    // ---- per-head softmax stats (warp h owns head h) ----
    const float ard = AR[d * HEADS + h];
    float selfl = AL[d * HEADS + h] + ard;
    selfl = selfl > 0.f ? selfl : 0.2f * selfl;
    float m = selfl;
    for (int i = lane; i < deg; i += 32) {
        int s = csrc[beg + i];
        float v = AL[s * HEADS + h] + ard;
        v = v > 0.f ? v : 0.2f * v;
        m = fmaxf(m, v);
    }
#pragma unroll
    for (int o = 16; o; o >>= 1) m = fmaxf(m, __shfl_xor_sync(0xffffffffu, m, o));
    // self-loop term contributed by lane 0 ONLY
    float ssum = (lane == 0) ? __expf(selfl - m) : 0.f;
    for (int i = lane; i < deg; i += 32) {
        int s = csrc[beg + i];
        float v = AL[s * HEADS + h] + ard;
        v = v > 0.f ? v : 0.2f * v;
        ssum += __expf(v - m);
    }
#pragma unroll
    for (int o = 16; o; o >>= 1) ssum += __shfl_xor_sync(0xffffffffu, ssum, o);
    const float inv = 1.f / ssum;

    __shared__ float alself[HEADS];
    __shared__ float wsh[256][HEADS];
    __shared__ int ssrc[256];
    if (!lane) alself[h] = __expf(selfl - m) * inv;
    __syncthreads();

    // per-vector head index (vector fully inside one head since C % 4 == 0)
    int hidx[NV];
#pragma unroll
    for (int j = 0; j < NV; j++) hidx[j] = ((j * 256 + tid) * VEC) / C;

    // ---- accumulate: self-loop first (vectorized) ----
    float acc[WPT];
    {
        const float* hd = H + (size_t)d * W;
#pragma unroll
        for (int j = 0; j < NV; j++) {
            float a = alself[hidx[j]];
            int e = (j * 256 + tid) * VEC;
            if (VEC == 4) {
                float4 v = *(const float4*)&hd[e];
                acc[j * 4 + 0] = a * v.x; acc[j * 4 + 1] = a * v.y;
                acc[j * 4 + 2] = a * v.z; acc[j * 4 + 3] = a * v.w;
            } else {
                float2 v = *(const float2*)&hd[e];
                acc[j * 2 + 0] = a * v.x; acc[j * 2 + 1] = a * v.y;
            }
        }
    }

    // ---- gather over incoming edges (chunks of 256), 2-edge unroll ----
    for (int base = 0; base < deg; base += 256) {
        int n = min(256, deg - base);
        for (int i = lane; i < n; i += 32) {
            int s = csrc[beg + base + i];
            if (h == 0) ssrc[i] = s;
            float v = AL[s * HEADS + h] + ard;
            v = v > 0.f ? v : 0.2f * v;
            wsh[i][h] = __expf(v - m) * inv;
        }
        __syncthreads();
        int i = 0;
        for (; i + 2 <= n; i += 2) {
            const float* h0 = H + (size_t)ssrc[i] * W;
            const float* h1 = H + (size_t)ssrc[i + 1] * W;
#pragma unroll
            for (int j = 0; j < NV; j++) {
                float a0 = wsh[i][hidx[j]];
                float a1 = wsh[i + 1][hidx[j]];
                int e = (j * 256 + tid) * VEC;
                if (VEC == 4) {
                    float4 v0 = *(const float4*)&h0[e];
                    float4 v1 = *(const float4*)&h1[e];
                    acc[j * 4 + 0] += a0 * v0.x + a1 * v1.x;
                    acc[j * 4 + 1] += a0 * v0.y + a1 * v1.y;
                    acc[j * 4 + 2] += a0 * v0.z + a1 * v1.z;
                    acc[j * 4 + 3] += a0 * v0.w + a1 * v1.w;
                } else {
                    float2 v0 = *(const float2*)&h0[e];
                    float2 v1 = *(const float2*)&h1[e];
                    acc[j * 2 + 0] += a0 * v0.x + a1 * v1.x;
                    acc[j * 2 + 1] += a0 * v0.y + a1 * v1.y;
                }
            }
        }
        if (i < n) {
            const float* h0 = H + (size_t)ssrc[i] * W;
#pragma unroll
            for (int j = 0; j < NV; j++) {
                float a0 = wsh[i][hidx[j]];
                int e = (j * 256 + tid) * VEC;
                if (VEC == 4) {
                    float4 v0 = *(const float4*)&h0[e];
                    acc[j * 4 + 0] += a0 * v0.x;
                    acc[j * 4 + 1] += a0 * v0.y;
                    acc[j * 4 + 2] += a0 * v0.z;
                    acc[j * 4 + 3] += a0 * v0.w;
                } else {
                    float2 v0 = *(const float2*)&h0[e];
                    acc[j * 2 + 0] += a0 * v0.x;
                    acc[j * 2 + 1] += a0 * v0.y;
                }
            }
        }
        __syncthreads();
    }

    // ---- fused epilogue ----
    __shared__ float sa[8], sb2[8];
    __shared__ float mu_sh, inv_sh;
    if (CONCAT) {
        float v[WPT];
        float s1 = 0.f, s2 = 0.f;
#pragma unroll
        for (int j = 0; j < NV; j++) {
            int e = (j * 256 + tid) * VEC;
            float4 bb = *(const float4*)&b[e];   // VEC==4 on concat layers
            float bv[4] = {bb.x, bb.y, bb.z, bb.w};
#pragma unroll
            for (int k = 0; k < VEC; k++) {
                float t = acc[j * VEC + k] + bv[k];
                t = t > 0.f ? t : (__expf(t) - 1.f);
                v[j * VEC + k] = t;
                s1 += t; s2 += t * t;
            }
        }
#pragma unroll
        for (int o = 16; o; o >>= 1) {
            s1 += __shfl_down_sync(0xffffffffu, s1, o);
            s2 += __shfl_down_sync(0xffffffffu, s2, o);
        }
        if (!lane) { sa[h] = s1; sb2[h] = s2; }
        __syncthreads();
        if (tid == 0) {
            float t1 = 0.f, t2 = 0.f;
#pragma unroll
            for (int w = 0; w < 8; w++) { t1 += sa[w]; t2 += sb2[w]; }
            float mu = t1 / W;
            float var = t2 / W - mu * mu;
            mu_sh = mu; inv_sh = rsqrtf(var + LN_EPS);
        }
        __syncthreads();
        float mu = mu_sh, istd = inv_sh;
#pragma unroll
        for (int j = 0; j < NV; j++) {
            int e = (j * 256 + tid) * VEC;
            float4 lsv = *(const float4*)&ls[e];
            float4 lbv = *(const float4*)&lb[e];
            float4 o;
            o.x = (v[j * VEC + 0] - mu) * istd * lsv.x + lbv.x;
            o.y = (v[j * VEC + 1] - mu) * istd * lsv.y + lbv.y;
            o.z = (v[j * VEC + 2] - mu) * istd * lsv.z + lbv.z;
            o.w = (v[j * VEC + 3] - mu) * istd * lsv.w + lbv.w;
            *(float4*)&X[(size_t)d * W + e] = o;
        }
    } else {
        // mean over heads -> C values, then ELU + LN over C
        __shared__ float arr[W];
#pragma unroll
        for (int j = 0; j < NV; j++) {
            int e = (j * 256 + tid) * VEC;
            if (VEC == 2) {
                float2 o; o.x = acc[j * 2 + 0]; o.y = acc[j * 2 + 1];
                *(float2*)&arr[e] = o;
            } else {
                float4 o; o.x = acc[j * 4 + 0]; o.y = acc[j * 4 + 1];
                o.z = acc[j * 4 + 2]; o.w = acc[j * 4 + 3];
                *(float4*)&arr[e] = o;
            }
        }
        __syncthreads();
        if (tid < C) {
            float t = 0.f;
#pragma unroll
            for (int hh = 0; hh < HEADS; hh++) t += arr[hh * C + tid];
            t = t * (1.f / HEADS) + b[tid];
            t = t > 0.f ? t : (__expf(t) - 1.f);
            float s1 = t, s2 = t * t;
#pragma unroll
            for (int o = 16; o; o >>= 1) {
                s1 += __shfl_xor_sync(0xffffffffu, s1, o);
                s2 += __shfl_xor_sync(0xffffffffu, s2, o);
            }
            if (!lane) { sa[tid >> 5] = s1; sb2[tid >> 5] = s2; }
        }
        __syncthreads();
        if (tid < C) {
            float T1 = 0.f, T2 = 0.f;
#pragma unroll
            for (int w = 0; w < C / 32; w++) { T1 += sa[w]; T2 += sb2[w]; }
            float mu = T1 / C;
            float var = T2 / C - mu * mu;
            float istd = rsqrtf(var + LN_EPS);
            float t = 0.f;
#pragma unroll
            for (int hh = 0; hh < HEADS; hh++) t += arr[hh * C + tid];
            t = t * (1.f / HEADS) + b[tid];
            t = t > 0.f ? t : (__expf(t) - 1.f);
            X[(size_t)d * C + tid] = (t - mu) * istd * ls[tid] + lb[tid];
        }
    }
}

// ---------------- projection epilogue: LN then exact GELU ---------------------
__global__ void ln_gelu(const float* __restrict__ IN, const float* __restrict__ ls,
                        const float* __restrict__ lb, float* node_out, int ld) {
    int n = blockIdx.x;
    int i = threadIdx.x;  // blockDim = 256 = ld
    float v = IN[(size_t)n * ld + i];
    __shared__ float sa[8], sb[8];
    __shared__ float mu_sh, inv_sh;
    float s1 = v, s2 = v * v;
    int lane = threadIdx.x & 31, wid = threadIdx.x >> 5;
#pragma unroll
    for (int o = 16; o; o >>= 1) {
        s1 += __shfl_down_sync(0xffffffffu, s1, o);
        s2 += __shfl_down_sync(0xffffffffu, s2, o);
    }
    if (!lane) { sa[wid] = s1; sb[wid] = s2; }
    __syncthreads();
    if (threadIdx.x == 0) {
        float t1 = 0.f, t2 = 0.f;
        for (int w = 0; w < 8; w++) { t1 += sa[w]; t2 += sb[w]; }
        float mu = t1 / ld;
        float var = t2 / ld - mu * mu;
        mu_sh = mu; inv_sh = rsqrtf(var + LN_EPS);
    }
    __syncthreads();
    float y = (v - mu_sh) * inv_sh * ls[i] + lb[i];
    float g = 0.5f * y * (1.f + erff(y * 0.70710678118654752f));
    node_out[(size_t)n * ld + i] = g;
}

// ---------------- pooling ------------------------------------------------------
__global__ void compute_q(const float* __restrict__ node_out, const float* __restrict__ wq,
                          const float* __restrict__ bq, float* q, int N) {
    int warp = (blockIdx.x * blockDim.x + threadIdx.x) >> 5;
    int lane = threadIdx.x & 31;
    if (warp >= N) return;
    const float* v = node_out + (size_t)warp * 256;
    float s = 0.f;
#pragma unroll
    for (int c4 = lane; c4 < 64; c4 += 32) {
        float4 x = *(const float4*)&v[c4 << 2];
        float4 w = *(const float4*)&wq[c4 << 2];
        s += x.x * w.x + x.y * w.y + x.z * w.z + x.w * w.w;
    }
#pragma unroll
    for (int o = 16; o; o >>= 1) s += __shfl_down_sync(0xffffffffu, s, o);
    if (!lane) q[warp] = s + bq[0];
}

__global__ void softmax_reduce(const float* __restrict__ q, float* red, int N) {
    __shared__ float sh[32];
    int tid = threadIdx.x;
    float m = -INFINITY;
    for (int i = tid; i < N; i += blockDim.x) m = fmaxf(m, q[i]);
    int lane = tid & 31, wid = tid >> 5;
#pragma unroll
    for (int o = 16; o; o >>= 1) m = fmaxf(m, __shfl_down_sync(0xffffffffu, m, o));
    if (!lane) sh[wid] = m;
    __syncthreads();
    if (tid == 0) {
        float mm = -INFINITY;
        for (int w = 0; w < (int)(blockDim.x >> 5); w++) mm = fmaxf(mm, sh[w]);
        sh[0] = mm;
    }
    __syncthreads();
    float M = sh[0];
    __syncthreads();
    float s = 0.f;
    for (int i = tid; i < N; i += blockDim.x) s += __expf(q[i] - M);
#pragma unroll
    for (int o = 16; o; o >>= 1) s += __shfl_down_sync(0xffffffffu, s, o);
    if (!lane) sh[wid] = s;
    __syncthreads();
    if (tid == 0) {
        float ss = 0.f;
        for (int w = 0; w < (int)(blockDim.x >> 5); w++) ss += sh[w];
        red[0] = M; red[1] = ss;
    }
}

// one block per graph; nodes of graph b are [b*nper, (b+1)*nper)
__global__ void pool_kernel(const float* __restrict__ node_out, const float* __restrict__ q,
                            const float* __restrict__ red, float* out, int nper) {
    int b = blockIdx.x;
    int c = threadIdx.x;  // 256
    float M = red[0], S = red[1];
    float num = 0.f, den = 0.f;
    for (int i = 0; i < nper; i++) {
        int n = b * nper + i;
        float w = __expf(q[n] - M) / S;
        num += w * node_out[(size_t)n * 256 + c];
        den += w;
    }
    out[b * 256 + c] = num / fmaxf(den, 1e-8f);
}

// ---------------- launch -------------------------------------------------------
extern "C" void kernel_launch(void* const* d_in, const int* in_sizes, int n_in,
                              void* d_out, int out_size) {
    const float* xin = (const float*)d_in[0];
    const int* src = (const int*)d_in[1];
    const int* dst = (const int*)d_in[2];
    int E = in_sizes[1];
    int N = in_sizes[3];
    int B = out_size / 256 - N;
    float* out = (float*)d_out;
    float* graph_out = out;
    float* node_out = out + (size_t)B * 256;

    float *gH, *gX, *gP, *gAL, *gAR, *gQ, *gRED;
    int *gDEG, *gROW, *gCUR, *gCSRC;
    cudaGetSymbolAddress((void**)&gH, g_H);
    cudaGetSymbolAddress((void**)&gX, g_X);
    cudaGetSymbolAddress((void**)&gP, g_P);
    cudaGetSymbolAddress((void**)&gAL, g_AL);
    cudaGetSymbolAddress((void**)&gAR, g_AR);
    cudaGetSymbolAddress((void**)&gQ, g_Q);
    cudaGetSymbolAddress((void**)&gRED, g_RED);
    cudaGetSymbolAddress((void**)&gDEG, g_DEG);
    cudaGetSymbolAddress((void**)&gROW, g_ROW);
    cudaGetSymbolAddress((void**)&gCUR, g_CUR);
    cudaGetSymbolAddress((void**)&gCSRC, g_CSRC);

    cudaFuncSetAttribute(gemm_tf32_kernel,
                         cudaFuncAttributeMaxDynamicSharedMemorySize, GEMM_SMEM);

    // ---- CSR by destination ----
    zero_int<<<(N + 255) / 256, 256>>>(gDEG, N);
    deg_count<<<(E + 255) / 256, 256>>>(dst, gDEG, E);
    scan_kernel<<<1, 1024>>>(gDEG, gROW, gCUR, N);
    scatter_kernel<<<(E + 255) / 256, 256>>>(src, dst, gCUR, gCSRC, E);

    const float* x = xin;
    int K = in_sizes[0] / N;

    for (int l = 0; l < 3; l++) {
        int wi = 4 + 6 * l;
        const float* W  = (const float*)d_in[wi];
        const float* b  = (const float*)d_in[wi + 1];
        const float* as_ = (const float*)d_in[wi + 2];
        const float* ad  = (const float*)d_in[wi + 3];
        const float* ls = (const float*)d_in[wi + 4];
        const float* lb = (const float*)d_in[wi + 5];
        int C = in_sizes[wi + 2] / HEADS;
        int wdim = C * HEADS;

        dim3 ggrid(wdim / BN, (N + BM - 1) / BM);
        gemm_tf32_kernel<<<ggrid, 256, GEMM_SMEM>>>(x, W, nullptr, gH, N, wdim, K);

        attn_coef<<<(N * HEADS * 32 + 255) / 256, 256>>>(gH, as_, ad, gAL, gAR, N, C);

        if (l == 0)
            fused_gat_kernel<8, 4, true><<<N, 256>>>(gH, gAL, gAR, gROW, gCSRC, b, ls, lb, gX);
        else if (l == 1)
            fused_gat_kernel<4, 4, true><<<N, 256>>>(gH, gAL, gAR, gROW, gCSRC, b, ls, lb, gX);
        else
            fused_gat_kernel<2, 2, false><<<N, 256>>>(gH, gAL, gAR, gROW, gCSRC, b, ls, lb, gX);

        K = (l < 2) ? wdim : C;
        x = gX;
    }

    const float* wp = (const float*)d_in[22];
    const float* bp = (const float*)d_in[23];
    const float* lsp = (const float*)d_in[24];
    const float* lbp = (const float*)d_in[25];
    const float* wq = (const float*)d_in[26];
    const float* bq = (const float*)d_in[27];

    dim3 pgrid(256 / BN, (N + BM - 1) / BM);
    gemm_tf32_kernel<<<pgrid, 256, GEMM_SMEM>>>(x, wp, bp, gP, N, 256, K);
    ln_gelu<<<N, 256>>>(gP, lsp, lbp, node_out, 256);

    compute_q<<<(N * 32 + 255) / 256, 256>>>(node_out, wq, bq, gQ, N);
    softmax_reduce<<<1, 1024>>>(gQ, gRED, N);
    pool_kernel<<<B, 256>>>(node_out, gQ, gRED, graph_out, N / B);
}